// round 1
// baseline (speedup 1.0000x reference)
#include <cuda_runtime.h>
#include <cuda_bf16.h>
#include <math.h>

// Problem dims (fixed)
#define BATCH    4096
#define IN_DIM   512
#define NEURONS  1024
#define OUT_DIM  512
#define NBASIS   18      // NUM_KNOTS + DEGREE - 1 = 16 + 3 - 1

// Scratch (allocation-free rule: device globals)
__device__ float g_h [BATCH * NEURONS];   // 16 MB
__device__ float g_sp[BATCH * NEURONS];   // 16 MB

// ---------------------------------------------------------------------------
// Classic 128x128x8 register-blocked SGEMM. C[M,N] = A[M,K] @ B[K,N] + bias,
// optional ReLU. All dims multiples of tile sizes for this problem.
// ---------------------------------------------------------------------------
__global__ __launch_bounds__(256) void sgemm_kernel(
    const float* __restrict__ A, const float* __restrict__ B,
    const float* __restrict__ bias, float* __restrict__ C,
    int M, int N, int K, int relu)
{
    __shared__ float As[8][128];
    __shared__ float Bs[8][128];

    const int tid = threadIdx.x;
    const int tx  = tid & 15;          // 0..15 -> N direction
    const int ty  = tid >> 4;          // 0..15 -> M direction
    const int row0 = blockIdx.y * 128;
    const int col0 = blockIdx.x * 128;

    // A tile loaders: 128 rows x 8 k = 1024 floats, 256 thr * float4 along K
    const int a_row = tid >> 1;            // 0..127
    const int a_k   = (tid & 1) * 4;       // 0 or 4
    // B tile loaders: 8 rows x 128 cols
    const int b_row = tid >> 5;            // 0..7
    const int b_col = (tid & 31) * 4;      // 0..124

    float acc[8][8];
    #pragma unroll
    for (int i = 0; i < 8; i++)
        #pragma unroll
        for (int j = 0; j < 8; j++) acc[i][j] = 0.0f;

    for (int k0 = 0; k0 < K; k0 += 8) {
        float4 av = *(const float4*)(A + (size_t)(row0 + a_row) * K + k0 + a_k);
        As[a_k + 0][a_row] = av.x;
        As[a_k + 1][a_row] = av.y;
        As[a_k + 2][a_row] = av.z;
        As[a_k + 3][a_row] = av.w;
        float4 bv = *(const float4*)(B + (size_t)(k0 + b_row) * N + col0 + b_col);
        *(float4*)&Bs[b_row][b_col] = bv;
        __syncthreads();

        #pragma unroll
        for (int kk = 0; kk < 8; kk++) {
            float a_frag[8], b_frag[8];
            *(float4*)&a_frag[0] = *(const float4*)&As[kk][ty * 8];
            *(float4*)&a_frag[4] = *(const float4*)&As[kk][ty * 8 + 4];
            *(float4*)&b_frag[0] = *(const float4*)&Bs[kk][tx * 8];
            *(float4*)&b_frag[4] = *(const float4*)&Bs[kk][tx * 8 + 4];
            #pragma unroll
            for (int i = 0; i < 8; i++)
                #pragma unroll
                for (int j = 0; j < 8; j++)
                    acc[i][j] = fmaf(a_frag[i], b_frag[j], acc[i][j]);
        }
        __syncthreads();
    }

    // Epilogue: +bias, optional relu, float4 stores
    #pragma unroll
    for (int i = 0; i < 8; i++) {
        const int row = row0 + ty * 8 + i;
        float* cp = C + (size_t)row * N + col0 + tx * 8;
        #pragma unroll
        for (int j = 0; j < 8; j += 4) {
            const int col = col0 + tx * 8 + j;
            float4 v;
            v.x = acc[i][j + 0] + bias[col + 0];
            v.y = acc[i][j + 1] + bias[col + 1];
            v.z = acc[i][j + 2] + bias[col + 2];
            v.w = acc[i][j + 3] + bias[col + 3];
            if (relu) {
                v.x = fmaxf(v.x, 0.0f);
                v.y = fmaxf(v.y, 0.0f);
                v.z = fmaxf(v.z, 0.0f);
                v.w = fmaxf(v.w, 0.0f);
            }
            *(float4*)(cp + j) = v;
        }
    }
}

// ---------------------------------------------------------------------------
// Fused row min-max norm + uniform cubic B-spline activation.
// One block per row (1024 neurons), 256 threads x 4 elements.
// Knots are uniform with spacing h = 1/15 over [-3h, 1+3h]; for u in [0,1]
// the 18-basis Cox-de Boor recursion reduces to the 4-tap uniform cubic
// B-spline: sp[n] = sum_{c=0..3} w_c(s) * coeff[n, m+c],  m = floor(15u),
// s = 15u - m. Edge u==1 (eps underflow in fp32): m clamps to 15, s=0,
// w3=0 so the (out-of-range) 4th tap is clamped to index 17 harmlessly.
// ---------------------------------------------------------------------------
__global__ __launch_bounds__(256) void spline_kernel(
    const float* __restrict__ coeff, const float* __restrict__ sp_bias)
{
    __shared__ float s_mn[8], s_mx[8];

    const int row = blockIdx.x;
    const int tid = threadIdx.x;
    const float* hr = g_h + (size_t)row * NEURONS;

    float v[4];
    float mn =  3.0e38f;
    float mx = -3.0e38f;
    #pragma unroll
    for (int i = 0; i < 4; i++) {
        v[i] = hr[tid + 256 * i];
        mn = fminf(mn, v[i]);
        mx = fmaxf(mx, v[i]);
    }
    // warp reduce
    #pragma unroll
    for (int off = 16; off > 0; off >>= 1) {
        mn = fminf(mn, __shfl_xor_sync(0xFFFFFFFFu, mn, off));
        mx = fmaxf(mx, __shfl_xor_sync(0xFFFFFFFFu, mx, off));
    }
    if ((tid & 31) == 0) {
        s_mn[tid >> 5] = mn;
        s_mx[tid >> 5] = mx;
    }
    __syncthreads();
    mn = s_mn[0]; mx = s_mx[0];
    #pragma unroll
    for (int w = 1; w < 8; w++) {
        mn = fminf(mn, s_mn[w]);
        mx = fmaxf(mx, s_mx[w]);
    }

    const float inv = 1.0f / (mx - mn + 1e-8f);
    float* spr = g_sp + (size_t)row * NEURONS;

    #pragma unroll
    for (int i = 0; i < 4; i++) {
        const int n = tid + 256 * i;
        const float u = (v[i] - mn) * inv;
        float t = u * 15.0f;
        int m = (int)floorf(t);
        m = max(0, min(m, 15));
        const float s  = t - (float)m;
        const float s2 = s * s;
        const float s3 = s2 * s;
        const float os = 1.0f - s;
        const float w0 = (1.0f / 6.0f) * os * os * os;
        const float w1 = (1.0f / 6.0f) * (3.0f * s3 - 6.0f * s2 + 4.0f);
        const float w2 = (1.0f / 6.0f) * (-3.0f * s3 + 3.0f * s2 + 3.0f * s + 1.0f);
        const float w3 = (1.0f / 6.0f) * s3;

        const float* c = coeff + n * NBASIS + m;
        float r = w0 * c[0] + w1 * c[1] + w2 * c[2];
        const int i3 = min(m + 3, NBASIS - 1);
        r += w3 * coeff[n * NBASIS + i3];
        spr[n] = r + sp_bias[n];
    }
}

// ---------------------------------------------------------------------------
extern "C" void kernel_launch(void* const* d_in, const int* in_sizes, int n_in,
                              void* d_out, int out_size)
{
    const float* x       = (const float*)d_in[0];   // [4096, 512]
    const float* W1      = (const float*)d_in[1];   // [512, 1024]
    const float* b1      = (const float*)d_in[2];   // [1024]
    const float* coeff   = (const float*)d_in[3];   // [1024, 18]
    const float* sp_bias = (const float*)d_in[4];   // [1024]
    const float* W2      = (const float*)d_in[5];   // [1024, 512]
    const float* b2      = (const float*)d_in[6];   // [512]
    float*       out     = (float*)d_out;           // [4096, 512]

    float* h_ptr  = nullptr;
    float* sp_ptr = nullptr;
    cudaGetSymbolAddress((void**)&h_ptr,  g_h);
    cudaGetSymbolAddress((void**)&sp_ptr, g_sp);

    // GEMM1: h = x @ W1 + b1     [4096,1024]
    {
        dim3 grid(NEURONS / 128, BATCH / 128);
        sgemm_kernel<<<grid, 256>>>(x, W1, b1, h_ptr,
                                    BATCH, NEURONS, IN_DIM, 0);
    }
    // norm + spline: sp          [4096,1024]
    spline_kernel<<<BATCH, 256>>>(coeff, sp_bias);

    // GEMM2: out = relu(sp @ W2 + b2)   [4096,512]
    {
        dim3 grid(OUT_DIM / 128, BATCH / 128);
        sgemm_kernel<<<grid, 256>>>(sp_ptr, W2, b2, out,
                                    BATCH, OUT_DIM, NEURONS, 1);
    }
}

// round 3
// speedup vs baseline: 2.0303x; 2.0303x over previous
#include <cuda_runtime.h>
#include <cuda_bf16.h>
#include <cstdint>
#include <math.h>

#define BATCH    4096
#define IN_DIM   512
#define NEURONS  1024
#define OUT_DIM  512
#define NBASIS   18

// ---------------------------------------------------------------------------
// Scratch (allocation-free rule: device globals)
// ---------------------------------------------------------------------------
__device__ __align__(256) float         g_h    [BATCH * NEURONS];      // 16 MB
__device__ __align__(256) __nv_bfloat16 g_x_hi [BATCH * IN_DIM];
__device__ __align__(256) __nv_bfloat16 g_x_lo [BATCH * IN_DIM];
__device__ __align__(256) __nv_bfloat16 g_w1_hi[NEURONS * IN_DIM];     // [N,K] transposed
__device__ __align__(256) __nv_bfloat16 g_w1_lo[NEURONS * IN_DIM];
__device__ __align__(256) __nv_bfloat16 g_w2_hi[OUT_DIM * NEURONS];    // [N,K] transposed
__device__ __align__(256) __nv_bfloat16 g_w2_lo[OUT_DIM * NEURONS];
__device__ __align__(256) __nv_bfloat16 g_sp_hi[BATCH * NEURONS];
__device__ __align__(256) __nv_bfloat16 g_sp_lo[BATCH * NEURONS];

// ---------------------------------------------------------------------------
// PTX helpers (sm_80+ subset: cp.async, ldmatrix, mma.sync)
// ---------------------------------------------------------------------------
__device__ __forceinline__ uint32_t smem_u32(const void* p) {
    uint32_t a;
    asm("{ .reg .u64 t; cvta.to.shared.u64 t, %1; cvt.u32.u64 %0, t; }" : "=r"(a) : "l"(p));
    return a;
}
#define CP16(dst, src) \
    asm volatile("cp.async.cg.shared.global [%0], [%1], 16;" :: "r"(dst), "l"(src) : "memory")
#define CP_COMMIT() asm volatile("cp.async.commit_group;" ::: "memory")
#define CP_WAIT1()  asm volatile("cp.async.wait_group 1;" ::: "memory")

#define LDM4(r, addr)                                                        \
    asm volatile("ldmatrix.sync.aligned.m8n8.x4.shared.b16 {%0,%1,%2,%3}, [%4];" \
        : "=r"((r)[0]), "=r"((r)[1]), "=r"((r)[2]), "=r"((r)[3]) : "r"(addr))

#define MMA_BF16(c, a, b0, b1)                                               \
    asm volatile("mma.sync.aligned.m16n8k16.row.col.f32.bf16.bf16.f32 "      \
        "{%0,%1,%2,%3},{%4,%5,%6,%7},{%8,%9},{%0,%1,%2,%3};"                 \
        : "+f"((c)[0]), "+f"((c)[1]), "+f"((c)[2]), "+f"((c)[3])             \
        : "r"((a)[0]), "r"((a)[1]), "r"((a)[2]), "r"((a)[3]), "r"(b0), "r"(b1))

// ---------------------------------------------------------------------------
// Split-conversion prologue kernels
// ---------------------------------------------------------------------------
__device__ __forceinline__ void split2(float v, __nv_bfloat16& hi, __nv_bfloat16& lo) {
    hi = __float2bfloat16_rn(v);
    lo = __float2bfloat16_rn(v - __bfloat162float(hi));
}

__global__ __launch_bounds__(256) void conv_split_kernel(
    const float* __restrict__ src, __nv_bfloat16* __restrict__ hi,
    __nv_bfloat16* __restrict__ lo, int n)
{
    int i = blockIdx.x * 256 + threadIdx.x;
    if (i < n) split2(src[i], hi[i], lo[i]);
}

// out[c*R + r] = src[r*C + c]  (transpose + split). Coalesced writes.
__global__ __launch_bounds__(256) void conv_tsplit_kernel(
    const float* __restrict__ src, __nv_bfloat16* __restrict__ hi,
    __nv_bfloat16* __restrict__ lo, int R, int C)
{
    int i = blockIdx.x * 256 + threadIdx.x;
    if (i >= R * C) return;
    int c = i / R, r = i % R;
    split2(src[(size_t)r * C + c], hi[i], lo[i]);
}

// ---------------------------------------------------------------------------
// Split-bf16 3-pass GEMM on mma.sync.  C[M,Ntot] = A[M,K] @ B[Ntot,K]^T + bias
// CTA 128x128, 8 warps as 4(M) x 2(N) -> warp tile 32x64. BK=32, cp.async
// double buffer. Passes: Ahi*Bhi + Ahi*Blo + Alo*Bhi, fp32 accum.
// ---------------------------------------------------------------------------
#define BK          32
#define ROWB        80                    // 32 bf16 = 64B + 16B pad
#define TILEB       (128 * ROWB)          // 10240 B per operand tile
#define STAGEB      (4 * TILEB)           // Ahi, Alo, Bhi, Blo
#define GEMM_SMEM   (2 * STAGEB)          // 81920 B

__global__ __launch_bounds__(256, 1) void gemm_mma_kernel(
    const __nv_bfloat16* __restrict__ Ahi, const __nv_bfloat16* __restrict__ Alo,
    const __nv_bfloat16* __restrict__ Bhi, const __nv_bfloat16* __restrict__ Blo,
    const float* __restrict__ bias, float* __restrict__ C,
    int K, int Ntot, int relu)
{
    extern __shared__ char smem[];
    const uint32_t sb = smem_u32(smem);
    const int tid  = threadIdx.x;
    const int wid  = tid >> 5;
    const int lane = tid & 31;
    const int warp_m = wid & 3;          // 0..3 -> M
    const int warp_n = wid >> 2;         // 0..1 -> N
    const int m0 = blockIdx.y * 128;
    const int n0 = blockIdx.x * 128;

    const __nv_bfloat16* srcs[4] = {
        Ahi + (size_t)m0 * K, Alo + (size_t)m0 * K,
        Bhi + (size_t)n0 * K, Blo + (size_t)n0 * K };

    float acc[2][8][4];
    #pragma unroll
    for (int i = 0; i < 2; i++)
        #pragma unroll
        for (int j = 0; j < 8; j++)
            #pragma unroll
            for (int q = 0; q < 4; q++) acc[i][j][q] = 0.0f;

    const int NC = K / BK;

    auto issue = [&](int c, int s) {
        if (c < NC) {
            const int kc = c * BK;
            #pragma unroll
            for (int i = 0; i < 8; i++) {
                const int id   = tid + i * 256;        // 0..2047
                const int tile = id >> 9;              // 0..3
                const int rem  = id & 511;
                const int row  = rem >> 2;             // 0..127
                const int seg  = rem & 3;              // 0..3 (16B chunks)
                const __nv_bfloat16* src = srcs[tile] + (size_t)row * K + kc + seg * 8;
                const uint32_t dst = sb + s * STAGEB + tile * TILEB + row * ROWB + seg * 16;
                CP16(dst, src);
            }
        }
        CP_COMMIT();
    };

    issue(0, 0);
    issue(1, 1);

    // ldmatrix lane-derived addressing.
    // A x4 matrices: m0 rows0-7 k0 | m1 rows8-15 k0 | m2 rows0-7 k+16B | m3 rows8-15 k+16B
    const int a_row = ((lane >> 3) & 1) * 8 + (lane & 7);
    const int a_kb  = ((lane >> 4) & 1) * 16;
    // B x4 matrices: m0 n0-7 k0 | m1 n0-7 k+16B | m2 n8-15 k0 | m3 n8-15 k+16B
    const int b_nad = ((lane >> 4) & 1) * 8 + (lane & 7);
    const int b_kb  = ((lane >> 3) & 1) * 16;

    for (int c = 0; c < NC; c++) {
        const int s = c & 1;
        CP_WAIT1();
        __syncthreads();

        const uint32_t stage = sb + s * STAGEB;
        const uint32_t aHiB = stage + (warp_m * 32 + a_row) * ROWB + a_kb;
        const uint32_t aLoB = aHiB + TILEB;
        const uint32_t bHiB = stage + 2 * TILEB + (warp_n * 64 + b_nad) * ROWB + b_kb;
        const uint32_t bLoB = bHiB + TILEB;

        #pragma unroll
        for (int ks = 0; ks < 2; ks++) {
            const uint32_t ko = ks * 32;   // 16 bf16 = 32 bytes
            uint32_t ah[2][4], al[2][4], bh[4][4], bl[4][4];
            LDM4(ah[0], aHiB + ko);
            LDM4(ah[1], aHiB + 16 * ROWB + ko);
            LDM4(al[0], aLoB + ko);
            LDM4(al[1], aLoB + 16 * ROWB + ko);
            #pragma unroll
            for (int fn = 0; fn < 4; fn++) {
                LDM4(bh[fn], bHiB + fn * 16 * ROWB + ko);
                LDM4(bl[fn], bLoB + fn * 16 * ROWB + ko);
            }
            #pragma unroll
            for (int fm = 0; fm < 2; fm++) {
                #pragma unroll
                for (int fn = 0; fn < 4; fn++) {
                    #pragma unroll
                    for (int h = 0; h < 2; h++) {
                        const int f = fn * 2 + h;
                        MMA_BF16(acc[fm][f], ah[fm], bh[fn][h * 2], bh[fn][h * 2 + 1]);
                        MMA_BF16(acc[fm][f], ah[fm], bl[fn][h * 2], bl[fn][h * 2 + 1]);
                        MMA_BF16(acc[fm][f], al[fm], bh[fn][h * 2], bh[fn][h * 2 + 1]);
                    }
                }
            }
        }
        __syncthreads();
        issue(c + 2, s);
    }

    // Epilogue: acc -> C with bias / relu
    const int gr = lane >> 2;
    const int tq = lane & 3;
    #pragma unroll
    for (int fm = 0; fm < 2; fm++) {
        const int r0 = m0 + warp_m * 32 + fm * 16 + gr;
        #pragma unroll
        for (int f = 0; f < 8; f++) {
            const int col = n0 + warp_n * 64 + f * 8 + tq * 2;
            const float bx = bias[col], by = bias[col + 1];
            float v0 = acc[fm][f][0] + bx;
            float v1 = acc[fm][f][1] + by;
            float v2 = acc[fm][f][2] + bx;
            float v3 = acc[fm][f][3] + by;
            if (relu) {
                v0 = fmaxf(v0, 0.0f); v1 = fmaxf(v1, 0.0f);
                v2 = fmaxf(v2, 0.0f); v3 = fmaxf(v3, 0.0f);
            }
            *(float2*)(C + (size_t)r0 * Ntot + col)       = make_float2(v0, v1);
            *(float2*)(C + (size_t)(r0 + 8) * Ntot + col) = make_float2(v2, v3);
        }
    }
}

// ---------------------------------------------------------------------------
// Fused row min-max norm + uniform cubic B-spline; writes bf16 hi/lo splits.
// Knots uniform (h=1/15): Cox-de Boor collapses to the 4-tap uniform cubic
// B-spline closed form.
// ---------------------------------------------------------------------------
__global__ __launch_bounds__(256) void spline_kernel(
    const float* __restrict__ coeff, const float* __restrict__ sp_bias)
{
    __shared__ float s_mn[8], s_mx[8];

    const int row = blockIdx.x;
    const int tid = threadIdx.x;
    const float* hr = g_h + (size_t)row * NEURONS;

    float v[4];
    float mn =  3.0e38f, mx = -3.0e38f;
    #pragma unroll
    for (int i = 0; i < 4; i++) {
        v[i] = hr[tid + 256 * i];
        mn = fminf(mn, v[i]);
        mx = fmaxf(mx, v[i]);
    }
    #pragma unroll
    for (int off = 16; off > 0; off >>= 1) {
        mn = fminf(mn, __shfl_xor_sync(0xFFFFFFFFu, mn, off));
        mx = fmaxf(mx, __shfl_xor_sync(0xFFFFFFFFu, mx, off));
    }
    if ((tid & 31) == 0) { s_mn[tid >> 5] = mn; s_mx[tid >> 5] = mx; }
    __syncthreads();
    mn = s_mn[0]; mx = s_mx[0];
    #pragma unroll
    for (int w = 1; w < 8; w++) { mn = fminf(mn, s_mn[w]); mx = fmaxf(mx, s_mx[w]); }

    const float inv = 1.0f / (mx - mn + 1e-8f);

    #pragma unroll
    for (int i = 0; i < 4; i++) {
        const int n = tid + 256 * i;
        const float u = (v[i] - mn) * inv;
        float t = u * 15.0f;
        int m = (int)floorf(t);
        m = max(0, min(m, 15));
        const float s  = t - (float)m;
        const float s2 = s * s;
        const float s3 = s2 * s;
        const float os = 1.0f - s;
        const float w0 = (1.0f / 6.0f) * os * os * os;
        const float w1 = (1.0f / 6.0f) * (3.0f * s3 - 6.0f * s2 + 4.0f);
        const float w2 = (1.0f / 6.0f) * (-3.0f * s3 + 3.0f * s2 + 3.0f * s + 1.0f);
        const float w3 = (1.0f / 6.0f) * s3;

        const float* cf = coeff + n * NBASIS + m;
        float r = w0 * cf[0] + w1 * cf[1] + w2 * cf[2];
        const int i3 = min(m + 3, NBASIS - 1);
        r += w3 * coeff[n * NBASIS + i3];
        r += sp_bias[n];

        __nv_bfloat16 hi, lo;
        split2(r, hi, lo);
        g_sp_hi[(size_t)row * NEURONS + n] = hi;
        g_sp_lo[(size_t)row * NEURONS + n] = lo;
    }
}

// ---------------------------------------------------------------------------
extern "C" void kernel_launch(void* const* d_in, const int* in_sizes, int n_in,
                              void* d_out, int out_size)
{
    const float* x       = (const float*)d_in[0];   // [4096, 512]
    const float* W1      = (const float*)d_in[1];   // [512, 1024]
    const float* b1      = (const float*)d_in[2];   // [1024]
    const float* coeff   = (const float*)d_in[3];   // [1024, 18]
    const float* sp_bias = (const float*)d_in[4];   // [1024]
    const float* W2      = (const float*)d_in[5];   // [1024, 512]
    const float* b2      = (const float*)d_in[6];   // [512]
    float*       out     = (float*)d_out;           // [4096, 512]

    float *h_ptr = nullptr;
    __nv_bfloat16 *xh, *xl, *w1h, *w1l, *w2h, *w2l, *sph, *spl;
    cudaGetSymbolAddress((void**)&h_ptr, g_h);
    cudaGetSymbolAddress((void**)&xh,  g_x_hi);  cudaGetSymbolAddress((void**)&xl,  g_x_lo);
    cudaGetSymbolAddress((void**)&w1h, g_w1_hi); cudaGetSymbolAddress((void**)&w1l, g_w1_lo);
    cudaGetSymbolAddress((void**)&w2h, g_w2_hi); cudaGetSymbolAddress((void**)&w2l, g_w2_lo);
    cudaGetSymbolAddress((void**)&sph, g_sp_hi); cudaGetSymbolAddress((void**)&spl, g_sp_lo);

    cudaFuncSetAttribute(gemm_mma_kernel,
                         cudaFuncAttributeMaxDynamicSharedMemorySize, GEMM_SMEM);

    // Prologue: fp32 -> split-bf16 (x as-is; W1/W2 transposed to [N,K])
    {
        int n = BATCH * IN_DIM;
        conv_split_kernel<<<(n + 255) / 256, 256>>>(x, xh, xl, n);
    }
    conv_tsplit_kernel<<<(IN_DIM * NEURONS + 255) / 256, 256>>>(W1, w1h, w1l, IN_DIM, NEURONS);
    conv_tsplit_kernel<<<(NEURONS * OUT_DIM + 255) / 256, 256>>>(W2, w2h, w2l, NEURONS, OUT_DIM);

    // GEMM1: h = x @ W1 + b1   [4096,1024]
    {
        dim3 grid(NEURONS / 128, BATCH / 128);
        gemm_mma_kernel<<<grid, 256, GEMM_SMEM>>>(xh, xl, w1h, w1l, b1, h_ptr,
                                                  IN_DIM, NEURONS, 0);
    }
    // norm + spline -> split-bf16 sp
    spline_kernel<<<BATCH, 256>>>(coeff, sp_bias);

    // GEMM2: out = relu(sp @ W2 + b2)  [4096,512]
    {
        dim3 grid(OUT_DIM / 128, BATCH / 128);
        gemm_mma_kernel<<<grid, 256, GEMM_SMEM>>>(sph, spl, w2h, w2l, b2, out,
                                                  NEURONS, OUT_DIM, 1);
    }
}